// round 4
// baseline (speedup 1.0000x reference)
#include <cuda_runtime.h>

#define TPB 128
#define PREP_TPB 256

typedef unsigned long long u64;

// ---------------------------------------------------------------------------
// Constant bank image (floats):
//  [0,2048)    W1T interleaved: W1T[k*32+j] = W1[j*64+k]
//  [2048,2176) W2T:            W2T[k*4+i]  = W2[i*32+k]
//  [2176,2304) H1T:            H1T[k*32+o] = H1[o*4+k]
//  [2304,2816) H2T:            H2T[k*16+o] = H2[o*32+k]
//  [2816,2848) b1  [2848,2852) b2  [2852,2884) c1  [2884,2900) c2
//  [2900,2908) qcos [2908,2916) qsin
// ---------------------------------------------------------------------------
#define OFF_W1 0
#define OFF_W2 2048
#define OFF_H1 2176
#define OFF_H2 2304
#define OFF_B1 2816
#define OFF_B2 2848
#define OFF_C1 2852
#define OFF_C2 2884
#define OFF_QC 2900
#define OFF_QS 2908
#define CB_SIZE 2944

__constant__ float CB[CB_SIZE];

// ---------------- packed f32x2 helpers --------------------------------------
__device__ __forceinline__ u64 dup2(float x) {
    u64 r;
    unsigned u = __float_as_uint(x);
    asm("mov.b64 %0, {%1, %1};" : "=l"(r) : "r"(u));
    return r;
}
__device__ __forceinline__ u64 pack2(float lo, float hi) {
    u64 r;
    asm("mov.b64 %0, {%1, %2};" : "=l"(r) : "r"(__float_as_uint(lo)), "r"(__float_as_uint(hi)));
    return r;
}
__device__ __forceinline__ float2 unpack2(u64 v) {
    unsigned lo, hi;
    asm("mov.b64 {%0, %1}, %2;" : "=r"(lo), "=r"(hi) : "l"(v));
    return make_float2(__uint_as_float(lo), __uint_as_float(hi));
}
__device__ __forceinline__ u64 swap2(u64 v) {
    unsigned lo, hi;
    asm("mov.b64 {%0, %1}, %2;" : "=r"(lo), "=r"(hi) : "l"(v));
    u64 r;
    asm("mov.b64 %0, {%1, %2};" : "=l"(r) : "r"(hi), "r"(lo));
    return r;
}
__device__ __forceinline__ u64 fma2(u64 a, u64 b, u64 c) {
    u64 d;
    asm("fma.rn.f32x2 %0, %1, %2, %3;" : "=l"(d) : "l"(a), "l"(b), "l"(c));
    return d;
}
__device__ __forceinline__ u64 mul2(u64 a, u64 b) {
    u64 d;
    asm("mul.rn.f32x2 %0, %1, %2;" : "=l"(d) : "l"(a), "l"(b));
    return d;
}
__device__ __forceinline__ u64 add2(u64 a, u64 b) {
    u64 d;
    asm("add.rn.f32x2 %0, %1, %2;" : "=l"(d) : "l"(a), "l"(b));
    return d;
}
__device__ __forceinline__ float fast_tanh(float x) {
    float e = __expf(2.0f * x);
    return 1.0f - __fdividef(2.0f, e + 1.0f);
}

// ---------------- packed 4-qubit statevector --------------------------------
// P[m], m = w0*4 + w1*2 + w2, lanes: lo = w3=0, hi = w3=1. (wire0 = MSB)
template <int MB>
__device__ __forceinline__ void ry_packed(u64* P, float c, float s) {
    u64 cd = dup2(c), sd = dup2(s), nsd = dup2(-s);
#pragma unroll
    for (int m = 0; m < 8; m++) {
        if ((m & MB) == 0) {
            const int j = m | MB;
            u64 A = P[m], Bv = P[j];
            P[m] = fma2(cd, A, mul2(nsd, Bv));
            P[j] = fma2(sd, A, mul2(cd, Bv));
        }
    }
}
__device__ __forceinline__ void ry3_packed(u64* P, float c, float s) {
    u64 ca = dup2(c);
    u64 cb = pack2(-s, s);
#pragma unroll
    for (int m = 0; m < 8; m++) {
        u64 T = swap2(P[m]);
        P[m] = fma2(ca, P[m], mul2(cb, T));
    }
}
__device__ __forceinline__ void swapP(u64& a, u64& b) { u64 t = a; a = b; b = t; }

// ---------------- prep: transpose weights straight into CB ------------------
__global__ void prep_kernel(float* __restrict__ cb,
                            const float* __restrict__ W1, const float* __restrict__ W2,
                            const float* __restrict__ b1, const float* __restrict__ b2,
                            const float* __restrict__ qp, const float* __restrict__ H1,
                            const float* __restrict__ c1, const float* __restrict__ H2,
                            const float* __restrict__ c2) {
    const int t = threadIdx.x;
#pragma unroll
    for (int i = t; i < 2048; i += PREP_TPB) {
        int j = i >> 6, k = i & 63;
        cb[OFF_W1 + k * 32 + j] = W1[i];
    }
    if (t < 128) {
        int i = t >> 5, k = t & 31;
        cb[OFF_W2 + k * 4 + i] = W2[t];
    }
    if (t < 128) {
        int o = t >> 2, k = t & 3;
        cb[OFF_H1 + k * 32 + o] = H1[t];
    }
#pragma unroll
    for (int i = t; i < 512; i += PREP_TPB) {
        int o = i >> 5, k = i & 31;
        cb[OFF_H2 + k * 16 + o] = H2[i];
    }
    if (t < 32) cb[OFF_B1 + t] = b1[t];
    if (t < 4)  cb[OFF_B2 + t] = b2[t];
    if (t < 32) cb[OFF_C1 + t] = c1[t];
    if (t < 16) cb[OFF_C2 + t] = c2[t];
    if (t < 8) {
        float cc, ss;
        sincosf(0.5f * qp[t], &ss, &cc);
        cb[OFF_QC + t] = cc;
        cb[OFF_QS + t] = ss;
    }
}

// ---------------- main kernel: one batch row per thread ---------------------
__global__ __launch_bounds__(TPB) void qnet_kernel(
    const float* __restrict__ state, float* __restrict__ out, int B)
{
    const int b = blockIdx.x * TPB + threadIdx.x;
    if (b >= B) return;

    const ulonglong2* __restrict__ w1  = reinterpret_cast<const ulonglong2*>(CB + OFF_W1);
    const ulonglong2* __restrict__ w2  = reinterpret_cast<const ulonglong2*>(CB + OFF_W2);
    const ulonglong2* __restrict__ h1  = reinterpret_cast<const ulonglong2*>(CB + OFF_H1);
    const ulonglong2* __restrict__ h2w = reinterpret_cast<const ulonglong2*>(CB + OFF_H2);

    // ===== layer 1: h = relu(x @ W1^T + b1), FFMA2 packed over output pairs ==
    u64 a[16];
    {
        const u64* bp = reinterpret_cast<const u64*>(CB + OFF_B1);
#pragma unroll
        for (int p = 0; p < 16; p++) a[p] = bp[p];
    }
    const float4* xp = reinterpret_cast<const float4*>(state) + (size_t)b * 16;
#pragma unroll
    for (int k4 = 0; k4 < 16; k4++) {
        float4 v = xp[k4];
        float r[4] = {v.x, v.y, v.z, v.w};
#pragma unroll
        for (int kk = 0; kk < 4; kk++) {
            const int k = k4 * 4 + kk;
            u64 d = dup2(r[kk]);
#pragma unroll
            for (int q = 0; q < 8; q++) {
                ulonglong2 w = w1[k * 8 + q];
                a[2 * q]     = fma2(d, w.x, a[2 * q]);
                a[2 * q + 1] = fma2(d, w.y, a[2 * q + 1]);
            }
        }
    }
    float h[32];
#pragma unroll
    for (int p = 0; p < 16; p++) {
        float2 f = unpack2(a[p]);
        h[2 * p]     = fmaxf(f.x, 0.0f);
        h[2 * p + 1] = fmaxf(f.y, 0.0f);
    }

    // ===== layer 2: encoded = tanh(h @ W2^T + b2) ============================
    u64 e0, e1;
    {
        const u64* bp = reinterpret_cast<const u64*>(CB + OFF_B2);
        e0 = bp[0];
        e1 = bp[1];
#pragma unroll
        for (int k = 0; k < 32; k++) {
            ulonglong2 wa = w2[k];     // row k: outputs (0,1) and (2,3)
            u64 d = dup2(h[k]);
            e0 = fma2(d, wa.x, e0);
            e1 = fma2(d, wa.y, e1);
        }
    }

    // ===== quantum circuit (packed along wire-3 axis) ========================
    float z[4];
    {
        float2 f01 = unpack2(e0);
        float2 f23 = unpack2(e1);
        float enc[4] = {f01.x, f01.y, f23.x, f23.y};
        float ec[4], es[4];
#pragma unroll
        for (int i = 0; i < 4; i++) {
            float t = fast_tanh(enc[i]);
            __sincosf(0.5f * t, &es[i], &ec[i]);
        }
        // product state
        float A[4] = {ec[0] * ec[1], ec[0] * es[1], es[0] * ec[1], es[0] * es[1]};
        u64 CL0 = pack2(ec[2] * ec[3], ec[2] * es[3]);
        u64 CL1 = pack2(es[2] * ec[3], es[2] * es[3]);
        u64 P[8];
#pragma unroll
        for (int m = 0; m < 8; m++)
            P[m] = mul2(dup2(A[m >> 1]), (m & 1) ? CL1 : CL0);

#pragma unroll
        for (int layer = 0; layer < 2; layer++) {
            // CNOT(0,1): ctrl m-bit4, tgt m-bit2 -> renames
            swapP(P[4], P[6]);
            swapP(P[5], P[7]);
            // CNOT(1,2): ctrl m-bit2, tgt m-bit1 -> renames
            swapP(P[2], P[3]);
            swapP(P[6], P[7]);
            // CNOT(2,3): ctrl m-bit1, tgt lane -> lane swap where m-bit0 set
            P[1] = swap2(P[1]);
            P[3] = swap2(P[3]);
            P[5] = swap2(P[5]);
            P[7] = swap2(P[7]);
            // CNOT(3,0): ctrl lane-hi, tgt m-bit4 -> exchange hi lanes m <-> m+4
#pragma unroll
            for (int m = 0; m < 4; m++) {
                float2 fa = unpack2(P[m]);
                float2 fb = unpack2(P[m + 4]);
                P[m]     = pack2(fa.x, fb.y);
                P[m + 4] = pack2(fb.x, fa.y);
            }
            const int o = layer * 4;
            ry_packed<4>(P, CB[OFF_QC + o + 0], CB[OFF_QS + o + 0]);  // wire 0
            ry_packed<2>(P, CB[OFF_QC + o + 1], CB[OFF_QS + o + 1]);  // wire 1
            ry_packed<1>(P, CB[OFF_QC + o + 2], CB[OFF_QS + o + 2]);  // wire 2
            ry3_packed(P, CB[OFF_QC + o + 3], CB[OFF_QS + o + 3]);    // wire 3
        }

        // Z expectations (packed tree)
        u64 PP[8];
#pragma unroll
        for (int m = 0; m < 8; m++) PP[m] = mul2(P[m], P[m]);
        const u64 NEG1 = dup2(-1.0f);

        u64 Q01 = add2(PP[0], PP[1]);
        u64 Q23 = add2(PP[2], PP[3]);
        u64 Q45 = add2(PP[4], PP[5]);
        u64 Q67 = add2(PP[6], PP[7]);

        u64 Sa = add2(Q01, Q23);   // m < 4
        u64 Sb = add2(Q45, Q67);   // m >= 4
        u64 K  = fma2(Sb, NEG1, Sa);          // z0: sign by m-bit4
        u64 Hh = fma2(add2(Q23, Q67), NEG1, add2(Q01, Q45));  // z1: sign by m-bit2
        u64 Ev = add2(add2(PP[0], PP[2]), add2(PP[4], PP[6]));
        u64 Od = add2(add2(PP[1], PP[3]), add2(PP[5], PP[7]));
        u64 G  = fma2(Od, NEG1, Ev);          // z2: sign by m-bit1
        u64 D  = add2(Sa, Sb);                // z3: lane difference

        float2 fk = unpack2(K);  z[0] = fk.x + fk.y;
        float2 fh = unpack2(Hh); z[1] = fh.x + fh.y;
        float2 fg = unpack2(G);  z[2] = fg.x + fg.y;
        float2 fd = unpack2(D);  z[3] = fd.x - fd.y;
    }

    // ===== head: h2 = relu(z @ H1^T + c1), packed over output pairs ==========
    u64 g[16];
    {
        const u64* bp = reinterpret_cast<const u64*>(CB + OFF_C1);
#pragma unroll
        for (int p = 0; p < 16; p++) g[p] = bp[p];
    }
#pragma unroll
    for (int k = 0; k < 4; k++) {
        u64 d = dup2(z[k]);
#pragma unroll
        for (int q = 0; q < 8; q++) {
            ulonglong2 w = h1[k * 8 + q];
            g[2 * q]     = fma2(d, w.x, g[2 * q]);
            g[2 * q + 1] = fma2(d, w.y, g[2 * q + 1]);
        }
    }
    float hv[32];
#pragma unroll
    for (int p = 0; p < 16; p++) {
        float2 f = unpack2(g[p]);
        hv[2 * p]     = fmaxf(f.x, 0.0f);
        hv[2 * p + 1] = fmaxf(f.y, 0.0f);
    }

    // ===== out = tanh(h2 @ H2^T + c2), packed over output pairs ==============
    u64 oa[8];
    {
        const u64* bp = reinterpret_cast<const u64*>(CB + OFF_C2);
#pragma unroll
        for (int p = 0; p < 8; p++) oa[p] = bp[p];
    }
#pragma unroll
    for (int k = 0; k < 32; k++) {
        u64 d = dup2(hv[k]);
#pragma unroll
        for (int q = 0; q < 4; q++) {
            ulonglong2 w = h2w[k * 4 + q];
            oa[2 * q]     = fma2(d, w.x, oa[2 * q]);
            oa[2 * q + 1] = fma2(d, w.y, oa[2 * q + 1]);
        }
    }

    float4* o4 = reinterpret_cast<float4*>(out) + (size_t)b * 4;
#pragma unroll
    for (int t = 0; t < 4; t++) {
        float2 fa = unpack2(oa[2 * t]);
        float2 fb = unpack2(oa[2 * t + 1]);
        o4[t] = make_float4(fast_tanh(fa.x), fast_tanh(fa.y),
                            fast_tanh(fb.x), fast_tanh(fb.y));
    }
}

extern "C" void kernel_launch(void* const* d_in, const int* in_sizes, int n_in,
                              void* d_out, int out_size) {
    const float* state = (const float*)d_in[0];
    const float* W1    = (const float*)d_in[1];
    const float* b1    = (const float*)d_in[2];
    const float* W2    = (const float*)d_in[3];
    const float* b2    = (const float*)d_in[4];
    const float* qp    = (const float*)d_in[5];
    const float* H1    = (const float*)d_in[6];
    const float* c1    = (const float*)d_in[7];
    const float* H2    = (const float*)d_in[8];
    const float* c2    = (const float*)d_in[9];

    void* cb = nullptr;
    cudaGetSymbolAddress(&cb, CB);
    prep_kernel<<<1, PREP_TPB>>>((float*)cb, W1, W2, b1, b2, qp, H1, c1, H2, c2);

    const int B = in_sizes[0] / 64;
    const int grid = (B + TPB - 1) / TPB;
    qnet_kernel<<<grid, TPB>>>(state, (float*)d_out, B);
}